// round 3
// baseline (speedup 1.0000x reference)
#include <cuda_runtime.h>
#include <math.h>

// ---------------- problem constants ----------------
#define NGT   100000
#define NAG   20000
#define EGT   640000
#define ECM   320000
#define DGT   32
#define DAG   64
#define VIS   64
#define CMM   128
#define MSG   64
#define OUTD  5
#define NH    4

// ---------------- scratch (device globals; no cudaMalloc allowed) ----------------
__device__ __align__(128) float g_fs1[NGT * VIS];
__device__ __align__(128) float g_el1[NGT * NH];
__device__ __align__(128) float g_fs2[NGT * CMM];
__device__ __align__(128) float g_el2[NGT * NH];
__device__ __align__(128) float g_er1[NAG * NH];
__device__ __align__(128) float g_er2[NAG * NH];
__device__ __align__(128) float g_dst2[NAG * CMM];   // [h_vis1 | feat_agent]
__device__ __align__(128) float g_h[NAG * CMM];
__device__ __align__(128) float g_t128[NAG * CMM];
__device__ __align__(128) float g_m[NAG * MSG];
__device__ __align__(128) float g_y[NAG * MSG];
__device__ __align__(128) float g_gi[NAG * 3 * CMM];
__device__ __align__(128) float g_gh[NAG * 3 * CMM];
__device__ __align__(128) float g_v1[DAG * NH];
__device__ __align__(128) float g_v2[CMM * NH];

__device__ int g_cnt_gt[NAG];
__device__ int g_cur_gt[NAG];
__device__ int g_offs_gt[NAG + 1];
__device__ int g_csr_gt[EGT];
__device__ int g_cnt_cm[NAG];
__device__ int g_cur_cm[NAG];
__device__ int g_offs_cm[NAG + 1];
__device__ int g_csr_cm[ECM];

__device__ __forceinline__ float lrelu(float x) { return x >= 0.f ? x : 0.2f * x; }

// ---------------- init: zero counters ----------------
__global__ void init_kernel() {
    int t = blockIdx.x * blockDim.x + threadIdx.x;
    if (t < NAG) { g_cnt_gt[t] = 0; g_cur_gt[t] = 0; g_cnt_cm[t] = 0; g_cur_cm[t] = 0; }
}

// ---------------- fold W_dst @ a_r into v[k][h] ----------------
__global__ void v12_kernel(const float* __restrict__ w1_dst, const float* __restrict__ a1_r,
                           const float* __restrict__ w2_dst, const float* __restrict__ a2_r) {
    int t = threadIdx.x;           // 256 threads, one block
    {   // v1: [64][4], dh=16
        int k = t >> 2, h = t & 3;
        float s = 0.f;
        #pragma unroll
        for (int d = 0; d < 16; d++) s += w1_dst[k * VIS + h * 16 + d] * a1_r[h * 16 + d];
        g_v1[t] = s;
    }
    #pragma unroll
    for (int i = 0; i < 2; i++) {  // v2: [128][4], dh=32
        int idx = t + i * 256;
        int k = idx >> 2, h = idx & 3;
        float s = 0.f;
        #pragma unroll
        for (int d = 0; d < 32; d++) s += w2_dst[k * CMM + h * 32 + d] * a2_r[h * 32 + d];
        g_v2[idx] = s;
    }
}

// ---------------- generic tiled SGEMM: C = act(A[M,K] x B[K,N](ldb) + bias [+ C]) ----------------
#define FLAG_RELU 1
#define FLAG_ACC  2
__global__ void gemm_k(const float* __restrict__ A, const float* __restrict__ B,
                       const float* __restrict__ bias, float* __restrict__ C,
                       int M, int N, int K, int ldb, int flags) {
    __shared__ float As[16][68];
    __shared__ float Bs[16][68];
    int tid = threadIdx.x;
    int row0 = blockIdx.x * 64;
    int col0 = blockIdx.y * 64;
    int ty = tid >> 4, tx = tid & 15;
    float acc[4][4] = {};
    int arow = tid >> 2;            // 0..63
    int acol = (tid & 3) * 4;       // 0,4,8,12
    int brow = tid >> 4;            // 0..15
    int bcol = (tid & 15) * 4;      // 0..60

    for (int k0 = 0; k0 < K; k0 += 16) {
        float4 av = make_float4(0.f, 0.f, 0.f, 0.f);
        int gr = row0 + arow;
        if (gr < M) av = *(const float4*)(A + (size_t)gr * K + k0 + acol);
        As[acol + 0][arow] = av.x; As[acol + 1][arow] = av.y;
        As[acol + 2][arow] = av.z; As[acol + 3][arow] = av.w;
        float4 bv = *(const float4*)(B + (size_t)(k0 + brow) * ldb + col0 + bcol);
        *(float4*)&Bs[brow][bcol] = bv;
        __syncthreads();
        #pragma unroll
        for (int k = 0; k < 16; k++) {
            float4 a = *(float4*)&As[k][ty * 4];
            float4 b = *(float4*)&Bs[k][tx * 4];
            acc[0][0] += a.x * b.x; acc[0][1] += a.x * b.y; acc[0][2] += a.x * b.z; acc[0][3] += a.x * b.w;
            acc[1][0] += a.y * b.x; acc[1][1] += a.y * b.y; acc[1][2] += a.y * b.z; acc[1][3] += a.y * b.w;
            acc[2][0] += a.z * b.x; acc[2][1] += a.z * b.y; acc[2][2] += a.z * b.z; acc[2][3] += a.z * b.w;
            acc[3][0] += a.w * b.x; acc[3][1] += a.w * b.y; acc[3][2] += a.w * b.z; acc[3][3] += a.w * b.w;
        }
        __syncthreads();
    }
    int c0 = col0 + tx * 4;
    #pragma unroll
    for (int i = 0; i < 4; i++) {
        int r = row0 + ty * 4 + i;
        if (r < M) {
            float4 v = make_float4(acc[i][0], acc[i][1], acc[i][2], acc[i][3]);
            float* cp = C + (size_t)r * N + c0;
            if (flags & FLAG_ACC) {
                float4 o = *(float4*)cp;
                v.x += o.x; v.y += o.y; v.z += o.z; v.w += o.w;
            }
            if (bias) {
                v.x += bias[c0]; v.y += bias[c0 + 1]; v.z += bias[c0 + 2]; v.w += bias[c0 + 3];
            }
            if (flags & FLAG_RELU) {
                v.x = fmaxf(v.x, 0.f); v.y = fmaxf(v.y, 0.f); v.z = fmaxf(v.z, 0.f); v.w = fmaxf(v.w, 0.f);
            }
            *(float4*)cp = v;
        }
    }
}

// ---------------- el = sum over dh of fs * a_l ----------------
__global__ void el_kernel(const float* __restrict__ a1l, const float* __restrict__ a2l) {
    int t = blockIdx.x * blockDim.x + threadIdx.x;
    if (t < NGT * NH) {
        int i = t >> 2, h = t & 3;
        const float* f = g_fs1 + (size_t)i * VIS + h * 16;
        const float* a = a1l + h * 16;
        float s = 0.f;
        #pragma unroll
        for (int d = 0; d < 16; d++) s += f[d] * a[d];
        g_el1[t] = s;
    } else if (t < 2 * NGT * NH) {
        int u = t - NGT * NH;
        int i = u >> 2, h = u & 3;
        const float* f = g_fs2 + (size_t)i * CMM + h * 32;
        const float* a = a2l + h * 32;
        float s = 0.f;
        #pragma unroll
        for (int d = 0; d < 32; d++) s += f[d] * a[d];
        g_el2[u] = s;
    }
}

// ---------------- er1 = feat_agent @ v1 ----------------
__global__ void er1_kernel(const float* __restrict__ feat_agent) {
    int t = blockIdx.x * blockDim.x + threadIdx.x;
    if (t >= NAG * NH) return;
    int n = t >> 2, h = t & 3;
    const float* f = feat_agent + (size_t)n * DAG;
    float s = 0.f;
    #pragma unroll 8
    for (int k = 0; k < DAG; k++) s += f[k] * g_v1[k * NH + h];
    g_er1[t] = s;
}

// ---------------- er2 = dst2 @ v2 ----------------
__global__ void er2_kernel() {
    int t = blockIdx.x * blockDim.x + threadIdx.x;
    if (t >= NAG * NH) return;
    int n = t >> 2, h = t & 3;
    const float* f = g_dst2 + (size_t)n * CMM;
    float s = 0.f;
    #pragma unroll 8
    for (int k = 0; k < CMM; k++) s += f[k] * g_v2[k * NH + h];
    g_er2[t] = s;
}

// ---------------- CSR build ----------------
__global__ void count_kernel(const int* __restrict__ dst, int* __restrict__ cnt, int E) {
    int e = blockIdx.x * blockDim.x + threadIdx.x;
    if (e < E) atomicAdd(&cnt[dst[e]], 1);
}

__global__ void scan_kernel(const int* __restrict__ cnt, int* __restrict__ offs, int n) {
    __shared__ int sh[1024];
    __shared__ int carry;
    int tid = threadIdx.x;
    if (tid == 0) carry = 0;
    __syncthreads();
    for (int base = 0; base < n; base += 1024) {
        int v = (base + tid < n) ? cnt[base + tid] : 0;
        sh[tid] = v;
        __syncthreads();
        for (int off = 1; off < 1024; off <<= 1) {
            int t = (tid >= off) ? sh[tid - off] : 0;
            __syncthreads();
            sh[tid] += t;
            __syncthreads();
        }
        int c = carry;
        if (base + tid < n) offs[base + tid] = c + sh[tid] - v;
        __syncthreads();
        if (tid == 0) carry = c + sh[1023];
        __syncthreads();
    }
    if (tid == 0) offs[n] = carry;
}

__global__ void scatter_kernel(const int* __restrict__ src, const int* __restrict__ dst,
                               const int* __restrict__ offs, int* __restrict__ cur,
                               int* __restrict__ csr, int E) {
    int e = blockIdx.x * blockDim.x + threadIdx.x;
    if (e >= E) return;
    int d = dst[e];
    int p = atomicAdd(&cur[d], 1);
    csr[offs[d] + p] = src[e];
}

// ---------------- GAT1 aggregate (warp per dst; dh=16, 64 out) ----------------
__global__ void gat1_kernel(const float* __restrict__ feat_agent, const float* __restrict__ b1) {
    int w = (blockIdx.x * blockDim.x + threadIdx.x) >> 5;
    if (w >= NAG) return;
    int lane = threadIdx.x & 31;
    int beg = g_offs_gt[w], end = g_offs_gt[w + 1];
    float4 er = *(const float4*)&g_er1[w * 4];
    float m0 = -3.0e38f, m1 = -3.0e38f, m2 = -3.0e38f, m3 = -3.0e38f;
    for (int e = beg; e < end; e++) {
        int s = g_csr_gt[e];
        float4 el = *(const float4*)&g_el1[s * 4];
        m0 = fmaxf(m0, lrelu(el.x + er.x));
        m1 = fmaxf(m1, lrelu(el.y + er.y));
        m2 = fmaxf(m2, lrelu(el.z + er.z));
        m3 = fmaxf(m3, lrelu(el.w + er.w));
    }
    float d0 = 0.f, d1 = 0.f, d2 = 0.f, d3 = 0.f;
    float acc0 = 0.f, acc1 = 0.f;
    int hs = lane >> 4;  // col lane -> head hs (0/1); col 32+lane -> head 2+hs
    for (int e = beg; e < end; e++) {
        int s = g_csr_gt[e];
        float4 el = *(const float4*)&g_el1[s * 4];
        float p0 = __expf(lrelu(el.x + er.x) - m0);
        float p1 = __expf(lrelu(el.y + er.y) - m1);
        float p2 = __expf(lrelu(el.z + er.z) - m2);
        float p3 = __expf(lrelu(el.w + er.w) - m3);
        d0 += p0; d1 += p1; d2 += p2; d3 += p3;
        float pa = (hs == 0) ? p0 : p1;
        float pb = (hs == 0) ? p2 : p3;
        const float* fr = g_fs1 + (size_t)s * VIS;
        acc0 += pa * fr[lane];
        acc1 += pb * fr[32 + lane];
    }
    float da = (hs == 0) ? d0 : d1;
    float db = (hs == 0) ? d2 : d3;
    float ia = da > 0.f ? 1.f / da : 0.f;
    float ib = db > 0.f ? 1.f / db : 0.f;
    float fa0 = feat_agent[(size_t)w * DAG + lane];
    float fa1 = feat_agent[(size_t)w * DAG + 32 + lane];
    float o0 = fmaxf(acc0 * ia + fa0 + b1[lane], 0.f);
    float o1 = fmaxf(acc1 * ib + fa1 + b1[32 + lane], 0.f);
    float* dr = g_dst2 + (size_t)w * CMM;
    dr[lane] = o0; dr[32 + lane] = o1;
    dr[64 + lane] = fa0; dr[96 + lane] = fa1;    // concat feat_agent
}

// ---------------- GAT2 aggregate (warp per dst; dh=32, 128 out) ----------------
__global__ void gat2_kernel(const float* __restrict__ b2) {
    int w = (blockIdx.x * blockDim.x + threadIdx.x) >> 5;
    if (w >= NAG) return;
    int lane = threadIdx.x & 31;
    int beg = g_offs_gt[w], end = g_offs_gt[w + 1];
    float4 er = *(const float4*)&g_er2[w * 4];
    float m0 = -3.0e38f, m1 = -3.0e38f, m2 = -3.0e38f, m3 = -3.0e38f;
    for (int e = beg; e < end; e++) {
        int s = g_csr_gt[e];
        float4 el = *(const float4*)&g_el2[s * 4];
        m0 = fmaxf(m0, lrelu(el.x + er.x));
        m1 = fmaxf(m1, lrelu(el.y + er.y));
        m2 = fmaxf(m2, lrelu(el.z + er.z));
        m3 = fmaxf(m3, lrelu(el.w + er.w));
    }
    float d0 = 0.f, d1 = 0.f, d2 = 0.f, d3 = 0.f;
    float a0 = 0.f, a1 = 0.f, a2 = 0.f, a3 = 0.f;
    for (int e = beg; e < end; e++) {
        int s = g_csr_gt[e];
        float4 el = *(const float4*)&g_el2[s * 4];
        float p0 = __expf(lrelu(el.x + er.x) - m0);
        float p1 = __expf(lrelu(el.y + er.y) - m1);
        float p2 = __expf(lrelu(el.z + er.z) - m2);
        float p3 = __expf(lrelu(el.w + er.w) - m3);
        d0 += p0; d1 += p1; d2 += p2; d3 += p3;
        const float* fr = g_fs2 + (size_t)s * CMM;
        a0 += p0 * fr[lane];
        a1 += p1 * fr[32 + lane];
        a2 += p2 * fr[64 + lane];
        a3 += p3 * fr[96 + lane];
    }
    float i0 = d0 > 0.f ? 1.f / d0 : 0.f;
    float i1 = d1 > 0.f ? 1.f / d1 : 0.f;
    float i2 = d2 > 0.f ? 1.f / d2 : 0.f;
    float i3 = d3 > 0.f ? 1.f / d3 : 0.f;
    const float* dr = g_dst2 + (size_t)w * CMM;
    float* hr = g_h + (size_t)w * CMM;
    hr[lane]      = fmaxf(a0 * i0 + dr[lane]      + b2[lane],      0.f);
    hr[32 + lane] = fmaxf(a1 * i1 + dr[32 + lane] + b2[32 + lane], 0.f);
    hr[64 + lane] = fmaxf(a2 * i2 + dr[64 + lane] + b2[64 + lane], 0.f);
    hr[96 + lane] = fmaxf(a3 * i3 + dr[96 + lane] + b2[96 + lane], 0.f);
}

// ---------------- comm mailbox mean: y = segsum(m[src]) / max(deg,1) ----------------
__global__ void comm_agg_kernel() {
    int w = (blockIdx.x * blockDim.x + threadIdx.x) >> 5;
    if (w >= NAG) return;
    int lane = threadIdx.x & 31;
    int beg = g_offs_cm[w], end = g_offs_cm[w + 1];
    float a0 = 0.f, a1 = 0.f;
    for (int e = beg; e < end; e++) {
        int s = g_csr_cm[e];
        const float* mr = g_m + (size_t)s * MSG;
        a0 += mr[lane];
        a1 += mr[32 + lane];
    }
    int deg = end - beg;
    float inv = 1.f / (float)(deg > 0 ? deg : 1);
    g_y[(size_t)w * MSG + lane] = a0 * inv;
    g_y[(size_t)w * MSG + 32 + lane] = a1 * inv;
}

// ---------------- GRU elementwise combine ----------------
__global__ void gru_kernel(const float* __restrict__ zz) {
    int idx = blockIdx.x * blockDim.x + threadIdx.x;
    if (idx >= NAG * CMM) return;
    int n = idx >> 7, j = idx & 127;
    size_t base = (size_t)n * 384;
    float ir = g_gi[base + j],       hr = g_gh[base + j];
    float iz = g_gi[base + 128 + j], hz = g_gh[base + 128 + j];
    float in_ = g_gi[base + 256 + j], hn = g_gh[base + 256 + j];
    float r  = 1.f / (1.f + __expf(-(ir + hr)));
    float zg = 1.f / (1.f + __expf(-(iz + hz)));
    float nn = tanhf(in_ + r * hn);
    g_h[idx] = (1.f - zg) * nn + zg * zz[idx];
}

// ---------------- output head ----------------
__global__ void out_kernel(const float* __restrict__ W, const float* __restrict__ b,
                           float* __restrict__ out) {
    int idx = blockIdx.x * blockDim.x + threadIdx.x;
    if (idx >= NAG * OUTD) return;
    int n = idx / OUTD, j = idx % OUTD;
    const float* hr = g_h + (size_t)n * CMM;
    float s = b[j];
    #pragma unroll 8
    for (int k = 0; k < CMM; k++) s += hr[k] * W[k * OUTD + j];
    out[idx] = s;
}

// ---------------- host launch ----------------
static void gemm(const float* A, const float* B, const float* bias, float* C,
                 int M, int N, int K, int ldb, int flags) {
    dim3 grid((M + 63) / 64, N / 64);
    gemm_k<<<grid, 256>>>(A, B, bias, C, M, N, K, ldb, flags);
}

extern "C" void kernel_launch(void* const* d_in, const int* in_sizes, int n_in,
                              void* d_out, int out_size) {
    const float* feat_gt    = (const float*)d_in[0];
    const float* feat_agent = (const float*)d_in[1];
    const float* z          = (const float*)d_in[2];
    const int*   gt_src     = (const int*)d_in[3];
    const int*   gt_dst     = (const int*)d_in[4];
    const int*   comm_src   = (const int*)d_in[5];
    const int*   comm_dst   = (const int*)d_in[6];
    const float* w1_src     = (const float*)d_in[7];
    const float* w1_dst     = (const float*)d_in[8];
    const float* a1_l       = (const float*)d_in[9];
    const float* a1_r       = (const float*)d_in[10];
    const float* b1         = (const float*)d_in[11];
    const float* w2_src     = (const float*)d_in[12];
    const float* w2_dst     = (const float*)d_in[13];
    const float* a2_l       = (const float*)d_in[14];
    const float* a2_r       = (const float*)d_in[15];
    const float* b2         = (const float*)d_in[16];
    const float* enc_w1     = (const float*)d_in[17];
    const float* enc_b1     = (const float*)d_in[18];
    const float* enc_w2     = (const float*)d_in[19];
    const float* enc_b2     = (const float*)d_in[20];
    const float* gw_ih      = (const float*)d_in[21];
    const float* gw_hh      = (const float*)d_in[22];
    const float* gb_ih      = (const float*)d_in[23];
    const float* gb_hh      = (const float*)d_in[24];
    const float* out_w      = (const float*)d_in[25];
    const float* out_b      = (const float*)d_in[26];

    float *p_fs1, *p_fs2, *p_h, *p_t, *p_m, *p_y, *p_gi, *p_gh;
    int *p_cntg, *p_curg, *p_offg, *p_csrg, *p_cntc, *p_curc, *p_offc, *p_csrc;
    cudaGetSymbolAddress((void**)&p_fs1, g_fs1);
    cudaGetSymbolAddress((void**)&p_fs2, g_fs2);
    cudaGetSymbolAddress((void**)&p_h,   g_h);
    cudaGetSymbolAddress((void**)&p_t,   g_t128);
    cudaGetSymbolAddress((void**)&p_m,   g_m);
    cudaGetSymbolAddress((void**)&p_y,   g_y);
    cudaGetSymbolAddress((void**)&p_gi,  g_gi);
    cudaGetSymbolAddress((void**)&p_gh,  g_gh);
    cudaGetSymbolAddress((void**)&p_cntg, g_cnt_gt);
    cudaGetSymbolAddress((void**)&p_curg, g_cur_gt);
    cudaGetSymbolAddress((void**)&p_offg, g_offs_gt);
    cudaGetSymbolAddress((void**)&p_csrg, g_csr_gt);
    cudaGetSymbolAddress((void**)&p_cntc, g_cnt_cm);
    cudaGetSymbolAddress((void**)&p_curc, g_cur_cm);
    cudaGetSymbolAddress((void**)&p_offc, g_offs_cm);
    cudaGetSymbolAddress((void**)&p_csrc, g_csr_cm);

    // 1) init + folded dst-attention vectors
    init_kernel<<<(NAG + 255) / 256, 256>>>();
    v12_kernel<<<1, 256>>>(w1_dst, a1_r, w2_dst, a2_r);

    // 2) src projections
    gemm(feat_gt, w1_src, nullptr, p_fs1, NGT, VIS, DGT, VIS, 0);
    gemm(feat_gt, w2_src, nullptr, p_fs2, NGT, CMM, DGT, CMM, 0);

    // 3) per-node attention scalars
    el_kernel<<<(2 * NGT * NH + 255) / 256, 256>>>(a1_l, a2_l);
    er1_kernel<<<(NAG * NH + 255) / 256, 256>>>(feat_agent);

    // 4) CSR build for both edge lists
    count_kernel<<<(EGT + 255) / 256, 256>>>(gt_dst, p_cntg, EGT);
    count_kernel<<<(ECM + 255) / 256, 256>>>(comm_dst, p_cntc, ECM);
    scan_kernel<<<1, 1024>>>(p_cntg, p_offg, NAG);
    scan_kernel<<<1, 1024>>>(p_cntc, p_offc, NAG);
    scatter_kernel<<<(EGT + 255) / 256, 256>>>(gt_src, gt_dst, p_offg, p_curg, p_csrg, EGT);
    scatter_kernel<<<(ECM + 255) / 256, 256>>>(comm_src, comm_dst, p_offc, p_curc, p_csrc, ECM);

    // 5) GAT stage 1 -> dst2, then stage 2 -> h
    gat1_kernel<<<(NAG * 32 + 255) / 256, 256>>>(feat_agent, b1);
    er2_kernel<<<(NAG * NH + 255) / 256, 256>>>();
    gat2_kernel<<<(NAG * 32 + 255) / 256, 256>>>(b2);

    // 6) two comm steps
    const float* zz = z;
    for (int step = 0; step < 2; step++) {
        gemm(p_h, enc_w1, enc_b1, p_t, NAG, 128, CMM, 128, FLAG_RELU);
        gemm(p_t, enc_w2, enc_b2, p_m, NAG, MSG, 128, MSG, FLAG_RELU);
        comm_agg_kernel<<<(NAG * 32 + 255) / 256, 256>>>();
        // gi = h @ W_ih[0:128] + b_ih ; gi += y @ W_ih[128:192]
        gemm(p_h, gw_ih, gb_ih, p_gi, NAG, 384, CMM, 384, 0);
        gemm(p_y, gw_ih + (size_t)CMM * 384, nullptr, p_gi, NAG, 384, MSG, 384, FLAG_ACC);
        gemm(zz, gw_hh, gb_hh, p_gh, NAG, 384, CMM, 384, 0);
        gru_kernel<<<(NAG * CMM + 255) / 256, 256>>>(zz);
        zz = p_h;   // after update, zz == h
    }

    // 7) outputs: (h_out [NAG,5], zz [NAG,128]) flattened in order
    float* out = (float*)d_out;
    if (out_size == NAG * CMM) {
        cudaMemcpyAsync(out, p_h, (size_t)NAG * CMM * sizeof(float), cudaMemcpyDeviceToDevice);
    } else if (out_size == NAG * OUTD) {
        out_kernel<<<(NAG * OUTD + 255) / 256, 256>>>(out_w, out_b, out);
    } else {
        out_kernel<<<(NAG * OUTD + 255) / 256, 256>>>(out_w, out_b, out);
        cudaMemcpyAsync(out + NAG * OUTD, p_h, (size_t)NAG * CMM * sizeof(float),
                        cudaMemcpyDeviceToDevice);
    }
}